// round 13
// baseline (speedup 1.0000x reference)
#include <cuda_runtime.h>

#define Dd     3
#define HID    64
#define WIDTH  64
#define BATCH  500000
#define BLOCKP (Dd * WIDTH)         // 192
#define P3N    (3 * BLOCKP + WIDTH) // 640

#define TPB    128
#define EPT    4                     // 2 f32x2 pairs per thread
#define NPAIR  2
#define GRID   ((BATCH / EPT + TPB - 1) / TPB)   // 977

typedef unsigned long long ull;

// Params, packed-duplicated for f32x2 math. Per hidden unit j, 4 float4s:
//  [4j+0] = {W0,W0,W1,W1}
//  [4j+1] = {W2,W2,B,B}
//  [4j+2] = {U0/64,U0/64,U1/64,U1/64}
//  [4j+3] = {U2/64,U2/64,wu/64,wu/64}
__device__ float4 g_p4[4 * WIDTH];

// ---------------------------------------------------------------------------
// helpers
// ---------------------------------------------------------------------------
__device__ __forceinline__ ull ffma2(ull a, ull b, ull c) {
    ull d;
    asm("fma.rn.f32x2 %0, %1, %2, %3;" : "=l"(d) : "l"(a), "l"(b), "l"(c));
    return d;
}
__device__ __forceinline__ ull fmul2(ull a, ull b) {
    ull d;
    asm("mul.rn.f32x2 %0, %1, %2;" : "=l"(d) : "l"(a), "l"(b));
    return d;
}
__device__ __forceinline__ ull pack2(float lo, float hi) {
    ull d;
    asm("mov.b64 %0, {%1, %2};" : "=l"(d) : "f"(lo), "f"(hi));
    return d;
}
__device__ __forceinline__ void unpack2(ull v, float& lo, float& hi) {
    asm("mov.b64 {%0, %1}, %2;" : "=f"(lo), "=f"(hi) : "l"(v));
}

// Packed tanh: f32x2 pre-activation -> f16x2 (one cvt) -> ONE
// tanh.approx.f16x2 MUFU op -> upconvert both halves to f32 -> repack.
// Halves MUFU instruction count vs 2x tanh.approx.f32. Pure PTX, no
// half-library types.
__device__ __forceinline__ ull tanh2_f16(ull pre2) {
    float plo, phi;
    unpack2(pre2, plo, phi);
    unsigned p16, h16;
    // pack two f32 into one f16x2 register (hi = phi, lo = plo)
    asm("cvt.rn.f16x2.f32 %0, %1, %2;" : "=r"(p16) : "f"(phi), "f"(plo));
    asm("tanh.approx.f16x2 %0, %1;" : "=r"(h16) : "r"(p16));
    float hlo, hhi;
    asm("{\n\t"
        ".reg .f16 lo, hi;\n\t"
        "mov.b32 {lo, hi}, %2;\n\t"
        "cvt.f32.f16 %0, lo;\n\t"
        "cvt.f32.f16 %1, hi;\n\t"
        "}"
        : "=f"(hlo), "=f"(hhi) : "r"(h16));
    return pack2(hlo, hhi);
}

// ---------------------------------------------------------------------------
// Kernel 1: hypernet, 4 blocks. Block b produces j in [16b, 16b+16).
// All global loads issued into registers at kernel entry. PDL producer.
// ---------------------------------------------------------------------------
__global__ void __launch_bounds__(256)
hyper_kernel(const float* __restrict__ t,
             const float* __restrict__ fc1_w,
             const float* __restrict__ fc1_b,
             const float* __restrict__ fc2_w,
             const float* __restrict__ fc2_b,
             const float* __restrict__ fc3_w,
             const float* __restrict__ fc3_b)
{
#if __CUDA_ARCH__ >= 900
    cudaTriggerProgrammaticLaunchCompletion();
#endif

    __shared__ float p1[HID];
    __shared__ float p2[HID];
    __shared__ float p3loc[160];

    const int tid = threadIdx.x;
    const int b   = blockIdx.x;

    // ---- issue ALL global loads up front ----
    float tv = 0.f, w1v = 0.f, b1v = 0.f, b2v = 0.f;
    if (tid < HID) {
        tv  = t[0];
        w1v = fc1_w[tid];
        b1v = fc1_b[tid];
        b2v = fc2_b[tid];
    }
    float4 r2[16];
    if (tid < HID) {
        const float4* row = reinterpret_cast<const float4*>(fc2_w + tid * HID);
        #pragma unroll
        for (int i = 0; i < 16; i++) r2[i] = row[i];
    }
    int grow = 0;
    float4 r3[16];
    float b3v = 0.f;
    if (tid < 160) {
        if      (tid < 48)  grow = 48 * b + tid;
        else if (tid < 96)  grow = BLOCKP + 48 * b + (tid - 48);
        else if (tid < 144) grow = 2 * BLOCKP + 48 * b + (tid - 96);
        else                grow = 3 * BLOCKP + 16 * b + (tid - 144);
        const float4* row = reinterpret_cast<const float4*>(fc3_w + grow * HID);
        #pragma unroll
        for (int i = 0; i < 16; i++) r3[i] = row[i];
        b3v = fc3_b[grow];
    }

    // ---- stage 1 ----
    if (tid < HID) {
        p1[tid] = tanhf(tv * w1v + b1v);
    }
    __syncthreads();

    // ---- stage 2 ----
    if (tid < HID) {
        float a0 = 0.f, a1 = 0.f, a2 = 0.f, a3 = 0.f;
        #pragma unroll
        for (int i = 0; i < 16; i++) {
            const float* pp = p1 + 4 * i;
            a0 = fmaf(r2[i].x, pp[0], a0);
            a1 = fmaf(r2[i].y, pp[1], a1);
            a2 = fmaf(r2[i].z, pp[2], a2);
            a3 = fmaf(r2[i].w, pp[3], a3);
        }
        p2[tid] = tanhf((a0 + a1) + (a2 + a3) + b2v);
    }
    __syncthreads();

    // ---- stage 3 ----
    if (tid < 160) {
        float a0 = 0.f, a1 = 0.f, a2 = 0.f, a3 = 0.f;
        #pragma unroll
        for (int i = 0; i < 16; i++) {
            const float* pp = p2 + 4 * i;
            a0 = fmaf(r3[i].x, pp[0], a0);
            a1 = fmaf(r3[i].y, pp[1], a1);
            a2 = fmaf(r3[i].z, pp[2], a2);
            a3 = fmaf(r3[i].w, pp[3], a3);
        }
        p3loc[tid] = (a0 + a1) + (a2 + a3) + b3v;
    }
    __syncthreads();

    // ---- assemble; fold 1/WIDTH into U and wu ----
    const float inv = 1.0f / (float)WIDTH;
    if (tid < 16) {
        const int j = 16 * b + tid;
        float w[3], u[3];
        #pragma unroll
        for (int d = 0; d < 3; d++) {
            w[d] = p3loc[3 * tid + d];
            float ur = p3loc[48 + 3 * tid + d];
            float g  = p3loc[96 + 3 * tid + d];
            float sg = 1.0f / (1.0f + expf(-g));
            u[d] = ur * sg * inv;
        }
        float wu = fmaf(w[0], u[0], fmaf(w[1], u[1], w[2] * u[2]));
        float bb = p3loc[144 + tid];
        g_p4[4 * j + 0] = make_float4(w[0], w[0], w[1], w[1]);
        g_p4[4 * j + 1] = make_float4(w[2], w[2], bb,  bb);
        g_p4[4 * j + 2] = make_float4(u[0], u[0], u[1], u[1]);
        g_p4[4 * j + 3] = make_float4(u[2], u[2], wu,  wu);
    }
}

// ---------------------------------------------------------------------------
// Kernel 2: main batch kernel. 4 elements/thread = 2 f32x2 pairs.
// tanh via ONE tanh.approx.f16x2 per pair (halves MUFU pressure).
// PDL consumer: preloads z, then grid-dep-sync before reading g_p4.
// ---------------------------------------------------------------------------
__global__ void __launch_bounds__(TPB, 6)
cnf_kernel(const float* __restrict__ z, float* __restrict__ out)
{
    __shared__ __align__(16) float4 sp4[4 * WIDTH];
    __shared__ float sS;

    const int tid  = threadIdx.x;
    const int base = (blockIdx.x * TPB + tid) * EPT;
    const bool active = (base < BATCH);   // BATCH % 4 == 0: all-or-nothing

    // preload z while hyper_kernel may still be running
    float4 a0, a1, a2;
    if (active) {
        const float4* z4 = reinterpret_cast<const float4*>(z + (size_t)base * 3);
        a0 = z4[0]; a1 = z4[1]; a2 = z4[2];
    }

#if __CUDA_ARCH__ >= 900
    cudaGridDependencySynchronize();
#endif

    // params global -> shared (256 entries, 2 per thread)
    sp4[tid]       = g_p4[tid];
    sp4[tid + TPB] = g_p4[tid + TPB];
    __syncthreads();

    // S = sum_j wu'/64 — warp 0 computes once per block
    if (tid < 32) {
        float s = sp4[4 * tid + 3].z + sp4[4 * (tid + 32) + 3].z;
        #pragma unroll
        for (int off = 16; off > 0; off >>= 1)
            s += __shfl_xor_sync(0xffffffffu, s, off);
        if (tid == 0) sS = s;
    }
    __syncthreads();

    if (!active) return;
    const float S = sS;

    // pack into f32x2 pairs: pair0 = elems {0,1}, pair1 = elems {2,3}
    ull zx2[NPAIR], zy2[NPAIR], zz2[NPAIR];
    zx2[0] = pack2(a0.x, a0.w);
    zy2[0] = pack2(a0.y, a1.x);
    zz2[0] = pack2(a0.z, a1.y);
    zx2[1] = pack2(a1.z, a2.y);
    zy2[1] = pack2(a1.w, a2.z);
    zz2[1] = pack2(a2.x, a2.w);

    ull d0[NPAIR], d1[NPAIR], d2[NPAIR], hw[NPAIR];
    #pragma unroll
    for (int p = 0; p < NPAIR; p++) { d0[p] = 0; d1[p] = 0; d2[p] = 0; hw[p] = 0; }

    const ulonglong2* spp = reinterpret_cast<const ulonglong2*>(sp4);

    // software-pipelined j loop: prefetch j+1 params while computing j
    ulonglong2 c0 = spp[0], c1 = spp[1], c2 = spp[2], c3 = spp[3];

    #pragma unroll 8
    for (int j = 0; j < WIDTH; j++) {
        const int jn = (j + 1) & (WIDTH - 1);
        ulonglong2 n0 = spp[4 * jn + 0];
        ulonglong2 n1 = spp[4 * jn + 1];
        ulonglong2 n2 = spp[4 * jn + 2];
        ulonglong2 n3 = spp[4 * jn + 3];

        #pragma unroll
        for (int p = 0; p < NPAIR; p++) {
            ull pre = ffma2(zz2[p], c1.x, c1.y);
            pre = ffma2(zy2[p], c0.y, pre);
            pre = ffma2(zx2[p], c0.x, pre);
            ull h2 = tanh2_f16(pre);           // 1 MUFU op for both lanes
            d0[p] = ffma2(h2, c2.x, d0[p]);
            d1[p] = ffma2(h2, c2.y, d1[p]);
            d2[p] = ffma2(h2, c3.x, d2[p]);
            ull hh = fmul2(h2, h2);
            hw[p] = ffma2(hh, c3.y, hw[p]);
        }

        c0 = n0; c1 = n1; c2 = n2; c3 = n3;
    }

    // epilogue (/WIDTH already folded into params)
    float od[12], lp[4];
    #pragma unroll
    for (int p = 0; p < NPAIR; p++) {
        float a, b;
        unpack2(d0[p], a, b); od[6 * p + 0] = a; od[6 * p + 3] = b;
        unpack2(d1[p], a, b); od[6 * p + 1] = a; od[6 * p + 4] = b;
        unpack2(d2[p], a, b); od[6 * p + 2] = a; od[6 * p + 5] = b;
        unpack2(hw[p], a, b);
        lp[2 * p + 0] = a - S;
        lp[2 * p + 1] = b - S;
    }

    float4* o = reinterpret_cast<float4*>(out + (size_t)base * 3);
    o[0] = make_float4(od[0], od[1], od[2],  od[3]);
    o[1] = make_float4(od[4], od[5], od[6],  od[7]);
    o[2] = make_float4(od[8], od[9], od[10], od[11]);

    *reinterpret_cast<float4*>(out + (size_t)(3 * BATCH) + base) =
        make_float4(lp[0], lp[1], lp[2], lp[3]);
}

// ---------------------------------------------------------------------------
// Launch: hyper, then cnf with programmatic stream serialization (PDL).
// ---------------------------------------------------------------------------
extern "C" void kernel_launch(void* const* d_in, const int* in_sizes, int n_in,
                              void* d_out, int out_size)
{
    const float* t     = (const float*)d_in[0];
    const float* z     = (const float*)d_in[1];
    // d_in[2] = logp_z (unused)
    const float* fc1_w = (const float*)d_in[3];
    const float* fc1_b = (const float*)d_in[4];
    const float* fc2_w = (const float*)d_in[5];
    const float* fc2_b = (const float*)d_in[6];
    const float* fc3_w = (const float*)d_in[7];
    const float* fc3_b = (const float*)d_in[8];
    float* out = (float*)d_out;

    hyper_kernel<<<4, 256>>>(t, fc1_w, fc1_b, fc2_w, fc2_b, fc3_w, fc3_b);

    cudaLaunchConfig_t cfg = {};
    cfg.gridDim  = dim3(GRID, 1, 1);
    cfg.blockDim = dim3(TPB, 1, 1);
    cfg.dynamicSmemBytes = 0;
    cudaLaunchAttribute attrs[1];
    attrs[0].id = cudaLaunchAttributeProgrammaticStreamSerialization;
    attrs[0].val.programmaticStreamSerializationAllowed = 1;
    cfg.attrs = attrs;
    cfg.numAttrs = 1;
    cudaLaunchKernelEx(&cfg, cnf_kernel, z, out);
}

// round 16
// speedup vs baseline: 1.0992x; 1.0992x over previous
#include <cuda_runtime.h>

#define Dd     3
#define HID    64
#define WIDTH  64
#define BATCH  500000
#define BLOCKP (Dd * WIDTH)         // 192
#define P3N    (3 * BLOCKP + WIDTH) // 640

#define TPB    128                   // 64 lower (j 0..31) + 64 upper (j 32..63)
#define EPT    4                     // 2 f32x2 pairs per thread-pair
#define NPAIR  2
#define PAIRS_PER_BLOCK 64           // element-groups (of 4) per block
#define GRID   ((BATCH / EPT + PAIRS_PER_BLOCK - 1) / PAIRS_PER_BLOCK)  // 1954

typedef unsigned long long ull;

// Params, packed-duplicated for f32x2 math. Per hidden unit j, 4 float4s:
//  [4j+0] = {W0,W0,W1,W1}
//  [4j+1] = {W2,W2,B,B}
//  [4j+2] = {U0/64,U0/64,U1/64,U1/64}
//  [4j+3] = {U2/64,U2/64,wu/64,wu/64}
__device__ float4 g_p4[4 * WIDTH];

// ---------------------------------------------------------------------------
// helpers
// ---------------------------------------------------------------------------
__device__ __forceinline__ ull ffma2(ull a, ull b, ull c) {
    ull d;
    asm("fma.rn.f32x2 %0, %1, %2, %3;" : "=l"(d) : "l"(a), "l"(b), "l"(c));
    return d;
}
__device__ __forceinline__ ull fmul2(ull a, ull b) {
    ull d;
    asm("mul.rn.f32x2 %0, %1, %2;" : "=l"(d) : "l"(a), "l"(b));
    return d;
}
__device__ __forceinline__ ull fadd2(ull a, ull b) {
    ull d;
    asm("add.rn.f32x2 %0, %1, %2;" : "=l"(d) : "l"(a), "l"(b));
    return d;
}
__device__ __forceinline__ ull pack2(float lo, float hi) {
    ull d;
    asm("mov.b64 %0, {%1, %2};" : "=l"(d) : "f"(lo), "f"(hi));
    return d;
}
__device__ __forceinline__ void unpack2(ull v, float& lo, float& hi) {
    asm("mov.b64 {%0, %1}, %2;" : "=f"(lo), "=f"(hi) : "l"(v));
}
__device__ __forceinline__ float tanha(float x) {
    float r;
    asm("tanh.approx.f32 %0, %1;" : "=f"(r) : "f"(x));
    return r;
}

// ---------------------------------------------------------------------------
// Kernel 1: hypernet, 4 blocks. Block b produces j in [16b, 16b+16).
// All global loads issued into registers at kernel entry. PDL producer.
// ---------------------------------------------------------------------------
__global__ void __launch_bounds__(256)
hyper_kernel(const float* __restrict__ t,
             const float* __restrict__ fc1_w,
             const float* __restrict__ fc1_b,
             const float* __restrict__ fc2_w,
             const float* __restrict__ fc2_b,
             const float* __restrict__ fc3_w,
             const float* __restrict__ fc3_b)
{
#if __CUDA_ARCH__ >= 900
    cudaTriggerProgrammaticLaunchCompletion();
#endif

    __shared__ float p1[HID];
    __shared__ float p2[HID];
    __shared__ float p3loc[160];

    const int tid = threadIdx.x;
    const int b   = blockIdx.x;

    // ---- issue ALL global loads up front ----
    float tv = 0.f, w1v = 0.f, b1v = 0.f, b2v = 0.f;
    if (tid < HID) {
        tv  = t[0];
        w1v = fc1_w[tid];
        b1v = fc1_b[tid];
        b2v = fc2_b[tid];
    }
    float4 r2[16];
    if (tid < HID) {
        const float4* row = reinterpret_cast<const float4*>(fc2_w + tid * HID);
        #pragma unroll
        for (int i = 0; i < 16; i++) r2[i] = row[i];
    }
    int grow = 0;
    float4 r3[16];
    float b3v = 0.f;
    if (tid < 160) {
        if      (tid < 48)  grow = 48 * b + tid;
        else if (tid < 96)  grow = BLOCKP + 48 * b + (tid - 48);
        else if (tid < 144) grow = 2 * BLOCKP + 48 * b + (tid - 96);
        else                grow = 3 * BLOCKP + 16 * b + (tid - 144);
        const float4* row = reinterpret_cast<const float4*>(fc3_w + grow * HID);
        #pragma unroll
        for (int i = 0; i < 16; i++) r3[i] = row[i];
        b3v = fc3_b[grow];
    }

    // ---- stage 1 ----
    if (tid < HID) {
        p1[tid] = tanhf(tv * w1v + b1v);
    }
    __syncthreads();

    // ---- stage 2 ----
    if (tid < HID) {
        float a0 = 0.f, a1 = 0.f, a2 = 0.f, a3 = 0.f;
        #pragma unroll
        for (int i = 0; i < 16; i++) {
            const float* pp = p1 + 4 * i;
            a0 = fmaf(r2[i].x, pp[0], a0);
            a1 = fmaf(r2[i].y, pp[1], a1);
            a2 = fmaf(r2[i].z, pp[2], a2);
            a3 = fmaf(r2[i].w, pp[3], a3);
        }
        p2[tid] = tanhf((a0 + a1) + (a2 + a3) + b2v);
    }
    __syncthreads();

    // ---- stage 3 ----
    if (tid < 160) {
        float a0 = 0.f, a1 = 0.f, a2 = 0.f, a3 = 0.f;
        #pragma unroll
        for (int i = 0; i < 16; i++) {
            const float* pp = p2 + 4 * i;
            a0 = fmaf(r3[i].x, pp[0], a0);
            a1 = fmaf(r3[i].y, pp[1], a1);
            a2 = fmaf(r3[i].z, pp[2], a2);
            a3 = fmaf(r3[i].w, pp[3], a3);
        }
        p3loc[tid] = (a0 + a1) + (a2 + a3) + b3v;
    }
    __syncthreads();

    // ---- assemble; fold 1/WIDTH into U and wu ----
    const float inv = 1.0f / (float)WIDTH;
    if (tid < 16) {
        const int j = 16 * b + tid;
        float w[3], u[3];
        #pragma unroll
        for (int d = 0; d < 3; d++) {
            w[d] = p3loc[3 * tid + d];
            float ur = p3loc[48 + 3 * tid + d];
            float g  = p3loc[96 + 3 * tid + d];
            float sg = 1.0f / (1.0f + expf(-g));
            u[d] = ur * sg * inv;
        }
        float wu = fmaf(w[0], u[0], fmaf(w[1], u[1], w[2] * u[2]));
        float bb = p3loc[144 + tid];
        g_p4[4 * j + 0] = make_float4(w[0], w[0], w[1], w[1]);
        g_p4[4 * j + 1] = make_float4(w[2], w[2], bb,  bb);
        g_p4[4 * j + 2] = make_float4(u[0], u[0], u[1], u[1]);
        g_p4[4 * j + 3] = make_float4(u[2], u[2], wu,  wu);
    }
}

// ---------------------------------------------------------------------------
// Kernel 2: main batch kernel, j-SPLIT.
// Block = 128 threads: lower 64 (j in [0,32)) and upper 64 (j in [32,64))
// cover the SAME 64 element-groups of 4. Upper half deposits partial sums
// in shared memory; lower half combines and stores. Doubles total warps
// (7816 -> ~36 resident warps/SM) at ~same total instruction count.
// ---------------------------------------------------------------------------
__global__ void __launch_bounds__(TPB)
cnf_kernel(const float* __restrict__ z, float* __restrict__ out)
{
    __shared__ __align__(16) float4 sp4[4 * WIDTH];
    __shared__ float sS;
    __shared__ ull comb[8 * PAIRS_PER_BLOCK];   // [k][lane64], k = 0..7

    const int tid    = threadIdx.x;
    const int half   = tid >> 6;        // 0 = lower (j 0..31), 1 = upper
    const int lane64 = tid & 63;

    const int pairIdx = blockIdx.x * PAIRS_PER_BLOCK + lane64;
    const int base    = pairIdx * EPT;
    const bool active = (base < BATCH);  // BATCH % 4 == 0: all-or-nothing

    // preload z while hyper_kernel may still be running
    float4 a0, a1, a2;
    if (active) {
        const float4* z4 = reinterpret_cast<const float4*>(z + (size_t)base * 3);
        a0 = z4[0]; a1 = z4[1]; a2 = z4[2];
    }

#if __CUDA_ARCH__ >= 900
    cudaGridDependencySynchronize();
#endif

    // params global -> shared (256 entries, 2 per thread)
    sp4[tid]       = g_p4[tid];
    sp4[tid + TPB] = g_p4[tid + TPB];
    __syncthreads();

    // S = sum_j wu'/64 — warp 0 computes once per block
    if (tid < 32) {
        float s = sp4[4 * tid + 3].z + sp4[4 * (tid + 32) + 3].z;
        #pragma unroll
        for (int off = 16; off > 0; off >>= 1)
            s += __shfl_xor_sync(0xffffffffu, s, off);
        if (tid == 0) sS = s;
    }
    __syncthreads();

    // pack into f32x2 pairs: pair0 = elems {0,1}, pair1 = elems {2,3}
    ull zx2[NPAIR], zy2[NPAIR], zz2[NPAIR];
    zx2[0] = pack2(a0.x, a0.w);
    zy2[0] = pack2(a0.y, a1.x);
    zz2[0] = pack2(a0.z, a1.y);
    zx2[1] = pack2(a1.z, a2.y);
    zy2[1] = pack2(a1.w, a2.z);
    zz2[1] = pack2(a2.x, a2.w);

    ull d0[NPAIR], d1[NPAIR], d2[NPAIR], hw[NPAIR];
    #pragma unroll
    for (int p = 0; p < NPAIR; p++) { d0[p] = 0; d1[p] = 0; d2[p] = 0; hw[p] = 0; }

    const ulonglong2* spp = reinterpret_cast<const ulonglong2*>(sp4);
    const int j0 = half << 5;           // 0 or 32

    if (active) {
        #pragma unroll 8
        for (int jj = 0; jj < WIDTH / 2; jj++) {
            const int j = j0 + jj;
            const ulonglong2 q0 = spp[4 * j + 0];
            const ulonglong2 q1 = spp[4 * j + 1];
            const ulonglong2 q2 = spp[4 * j + 2];
            const ulonglong2 q3 = spp[4 * j + 3];
            #pragma unroll
            for (int p = 0; p < NPAIR; p++) {
                ull pre = ffma2(zz2[p], q1.x, q1.y);
                pre = ffma2(zy2[p], q0.y, pre);
                pre = ffma2(zx2[p], q0.x, pre);
                float plo, phi;
                unpack2(pre, plo, phi);
                ull h2 = pack2(tanha(plo), tanha(phi));
                d0[p] = ffma2(h2, q2.x, d0[p]);
                d1[p] = ffma2(h2, q2.y, d1[p]);
                d2[p] = ffma2(h2, q3.x, d2[p]);
                ull hh = fmul2(h2, h2);
                hw[p] = ffma2(hh, q3.y, hw[p]);
            }
        }
    }

    // upper half deposits its partials (conflict-free: stride-1 in lane64)
    if (half) {
        comb[0 * 64 + lane64] = d0[0];
        comb[1 * 64 + lane64] = d1[0];
        comb[2 * 64 + lane64] = d2[0];
        comb[3 * 64 + lane64] = hw[0];
        comb[4 * 64 + lane64] = d0[1];
        comb[5 * 64 + lane64] = d1[1];
        comb[6 * 64 + lane64] = d2[1];
        comb[7 * 64 + lane64] = hw[1];
    }
    __syncthreads();

    if (half || !active) return;

    // lower half combines and stores
    const float S = sS;
    d0[0] = fadd2(d0[0], comb[0 * 64 + lane64]);
    d1[0] = fadd2(d1[0], comb[1 * 64 + lane64]);
    d2[0] = fadd2(d2[0], comb[2 * 64 + lane64]);
    hw[0] = fadd2(hw[0], comb[3 * 64 + lane64]);
    d0[1] = fadd2(d0[1], comb[4 * 64 + lane64]);
    d1[1] = fadd2(d1[1], comb[5 * 64 + lane64]);
    d2[1] = fadd2(d2[1], comb[6 * 64 + lane64]);
    hw[1] = fadd2(hw[1], comb[7 * 64 + lane64]);

    // epilogue (/WIDTH already folded into params)
    float od[12], lp[4];
    #pragma unroll
    for (int p = 0; p < NPAIR; p++) {
        float a, b;
        unpack2(d0[p], a, b); od[6 * p + 0] = a; od[6 * p + 3] = b;
        unpack2(d1[p], a, b); od[6 * p + 1] = a; od[6 * p + 4] = b;
        unpack2(d2[p], a, b); od[6 * p + 2] = a; od[6 * p + 5] = b;
        unpack2(hw[p], a, b);
        lp[2 * p + 0] = a - S;
        lp[2 * p + 1] = b - S;
    }

    float4* o = reinterpret_cast<float4*>(out + (size_t)base * 3);
    o[0] = make_float4(od[0], od[1], od[2],  od[3]);
    o[1] = make_float4(od[4], od[5], od[6],  od[7]);
    o[2] = make_float4(od[8], od[9], od[10], od[11]);

    *reinterpret_cast<float4*>(out + (size_t)(3 * BATCH) + base) =
        make_float4(lp[0], lp[1], lp[2], lp[3]);
}

// ---------------------------------------------------------------------------
// Launch: hyper, then cnf with programmatic stream serialization (PDL).
// ---------------------------------------------------------------------------
extern "C" void kernel_launch(void* const* d_in, const int* in_sizes, int n_in,
                              void* d_out, int out_size)
{
    const float* t     = (const float*)d_in[0];
    const float* z     = (const float*)d_in[1];
    // d_in[2] = logp_z (unused)
    const float* fc1_w = (const float*)d_in[3];
    const float* fc1_b = (const float*)d_in[4];
    const float* fc2_w = (const float*)d_in[5];
    const float* fc2_b = (const float*)d_in[6];
    const float* fc3_w = (const float*)d_in[7];
    const float* fc3_b = (const float*)d_in[8];
    float* out = (float*)d_out;

    hyper_kernel<<<4, 256>>>(t, fc1_w, fc1_b, fc2_w, fc2_b, fc3_w, fc3_b);

    cudaLaunchConfig_t cfg = {};
    cfg.gridDim  = dim3(GRID, 1, 1);
    cfg.blockDim = dim3(TPB, 1, 1);
    cfg.dynamicSmemBytes = 0;
    cudaLaunchAttribute attrs[1];
    attrs[0].id = cudaLaunchAttributeProgrammaticStreamSerialization;
    attrs[0].val.programmaticStreamSerializationAllowed = 1;
    cfg.attrs = attrs;
    cfg.numAttrs = 1;
    cudaLaunchKernelEx(&cfg, cnf_kernel, z, out);
}